// round 9
// baseline (speedup 1.0000x reference)
#include <cuda_runtime.h>
#include <cuda_bf16.h>
#include <string.h>

// Problem dims
#define IMGS 1024      // B*N = 32*32
#define HW   1024      // 32*32 pixels
#define C1O  64
#define C2O  128
#define HID  256
#define OUTD 128

// ---------------- scratch (device globals; device-code-only references) -------
__device__ float g_z1[(size_t)IMGS * C1O * HW];   // conv1 output (relu), 256 MB
__device__ float g_pool[IMGS * C2O];              // pooled conv2 output
__device__ float g_h0[IMGS * HID];                // fc output (masked)
__device__ float g_S1[32 * HID];                  // per-graph row sums of h0
__device__ float g_h1[IMGS * HID];                // sage1 output (relu)
__device__ float g_S2[32 * HID];                  // per-graph row sums of h1

// ---------------- packed f32x2 helpers (sm_103a FFMA2 path) -------------------
typedef unsigned long long ull;

__device__ __forceinline__ ull f32x2_pack(float lo, float hi) {
    ull r; asm("mov.b64 %0, {%1, %2};" : "=l"(r) : "f"(lo), "f"(hi)); return r;
}
__device__ __forceinline__ ull f32x2_bcast(float v) {
    ull r; asm("mov.b64 %0, {%1, %1};" : "=l"(r) : "f"(v)); return r;
}
__device__ __forceinline__ ull f32x2_of(float2 v) {
    ull r; memcpy(&r, &v, 8); return r;
}
__device__ __forceinline__ void f32x2_fma(ull& d, ull a, ull b) {
    asm("fma.rn.f32x2 %0, %1, %2, %0;" : "+l"(d) : "l"(a), "l"(b));
}
__device__ __forceinline__ void f32x2_unpack(ull v, float& lo, float& hi) {
    asm("mov.b64 {%0, %1}, %2;" : "=f"(lo), "=f"(hi) : "l"(v));
}

// =============================== conv1 ========================================
// One block per image. 256 threads, each owns 4 consecutive pixels (same row).
__global__ void conv1_kernel(const float* __restrict__ x,
                             const float* __restrict__ w,
                             const float* __restrict__ bias) {
    __shared__ float sIn[3 * 34 * 34];   // padded input, ~13.9 KB
    __shared__ float sW[C1O * 27];       // 6.9 KB
    __shared__ float sB[C1O];

    const int img = blockIdx.x;
    const int tid = threadIdx.x;

    for (int i = tid; i < C1O * 27; i += 256) sW[i] = w[i];
    if (tid < C1O) sB[tid] = bias[tid];

    const float* xin = x + (size_t)img * 3 * HW;
    for (int i = tid; i < 3 * 34 * 34; i += 256) {
        int c = i / 1156, r = i % 1156;
        int yy = r / 34, xx = r % 34;
        int yi = yy - 1, xi = xx - 1;
        float v = 0.f;
        if ((unsigned)yi < 32u && (unsigned)xi < 32u) v = xin[c * HW + yi * 32 + xi];
        sIn[i] = v;
    }
    __syncthreads();

    const int px0 = tid * 4;
    const int y = px0 >> 5, x0 = px0 & 31;
    float* outp = g_z1 + (size_t)img * C1O * HW;

    for (int oc = 0; oc < C1O; ++oc) {
        float bb = sB[oc];
        float acc0 = bb, acc1 = bb, acc2 = bb, acc3 = bb;
        const float* wp = &sW[oc * 27];
        #pragma unroll
        for (int ic = 0; ic < 3; ++ic) {
            #pragma unroll
            for (int kh = 0; kh < 3; ++kh) {
                float a0 = sIn[ic * 1156 + (y + kh) * 34 + x0 + 0];
                float a1 = sIn[ic * 1156 + (y + kh) * 34 + x0 + 1];
                float a2 = sIn[ic * 1156 + (y + kh) * 34 + x0 + 2];
                float a3 = sIn[ic * 1156 + (y + kh) * 34 + x0 + 3];
                float a4 = sIn[ic * 1156 + (y + kh) * 34 + x0 + 4];
                float a5 = sIn[ic * 1156 + (y + kh) * 34 + x0 + 5];
                float w0 = wp[ic * 9 + kh * 3 + 0];
                float w1 = wp[ic * 9 + kh * 3 + 1];
                float w2 = wp[ic * 9 + kh * 3 + 2];
                acc0 += a0 * w0 + a1 * w1 + a2 * w2;
                acc1 += a1 * w0 + a2 * w1 + a3 * w2;
                acc2 += a2 * w0 + a3 * w1 + a4 * w2;
                acc3 += a3 * w0 + a4 * w1 + a5 * w2;
            }
        }
        float* op = outp + oc * HW + px0;
        op[0] = fmaxf(acc0, 0.f);
        op[1] = fmaxf(acc1, 0.f);
        op[2] = fmaxf(acc2, 0.f);
        op[3] = fmaxf(acc3, 0.f);
    }
}

// ====================== conv2 + bias + relu + avgpool (fused, f32x2) ==========
// grid (8 oc-groups, 1024 images). 256 threads. Each thread: 4 px x 16 oc,
// accumulated as 2 packed f32x2 pairs per oc. fma.rn.f32x2 = 2 fp32 FMA/instr,
// halving fma-pipe issue count vs scalar FFMA (the measured bottleneck).
#define ICC 8
#define NCHUNK (C1O / ICC)                   // 8

__global__ void __launch_bounds__(256, 1)
conv2_pool_kernel(const float* __restrict__ w2, const float* __restrict__ b2) {
    __shared__ float sA[ICC * 34 * 34];      // [8][34][34], 37 KB
    __shared__ float sW[16 * ICC * 12];      // [16][8][12] (9 padded to 12), 6 KB
    __shared__ float red[16][8];

    const int og  = blockIdx.x;      // 0..7
    const int img = blockIdx.y;
    const int tid = threadIdx.x;
    const int px0 = tid * 4;
    const int y = px0 >> 5, x0 = px0 & 31;   // x0 multiple of 4 -> 16B aligned

    ull acc0[16], acc1[16];          // acc0 = px{0,1}, acc1 = px{2,3}
    #pragma unroll
    for (int o = 0; o < 16; ++o) { acc0[o] = 0ull; acc1[o] = 0ull; }

    for (int cc = 0; cc < NCHUNK; ++cc) {
        __syncthreads();
        // stage padded input chunk (8 channels)
        const float* zin = g_z1 + (size_t)img * C1O * HW + (size_t)cc * ICC * HW;
        for (int i = tid; i < ICC * 1156; i += 256) {
            int c = i / 1156, r = i % 1156;
            int yy = r / 34, xx = r % 34;
            int yi = yy - 1, xi = xx - 1;
            float v = 0.f;
            if ((unsigned)yi < 32u && (unsigned)xi < 32u) v = zin[c * HW + yi * 32 + xi];
            sA[i] = v;
        }
        // stage weights for this oc-group / ic-chunk
        for (int i = tid; i < 16 * ICC * 9; i += 256) {
            int ocl = i / (ICC * 9);
            int r   = i % (ICC * 9);
            int icl = r / 9, t = r % 9;
            sW[(ocl * ICC + icl) * 12 + t] =
                w2[(((og * 16 + ocl) * C1O) + cc * ICC + icl) * 9 + t];
        }
        __syncthreads();

        #pragma unroll
        for (int ic = 0; ic < ICC; ++ic) {
            // Activation pairs for the 3 stencil rows:
            // p[kh][j] = (a_j, a_{j+1}) for j = 0..4 over the 6-wide window.
            ull p[3][5];
            #pragma unroll
            for (int kh = 0; kh < 3; ++kh) {
                const float2* row =
                    (const float2*)&sA[ic * 1156 + (y + kh) * 34 + x0];
                float2 a01 = row[0], a23 = row[1], a45 = row[2];  // LDS.64 x3
                p[kh][0] = f32x2_of(a01);
                p[kh][1] = f32x2_pack(a01.y, a23.x);
                p[kh][2] = f32x2_of(a23);
                p[kh][3] = f32x2_pack(a23.y, a45.x);
                p[kh][4] = f32x2_of(a45);
            }
            #pragma unroll
            for (int ocl = 0; ocl < 16; ++ocl) {
                const float* wp = &sW[(ocl * ICC + ic) * 12];
                #pragma unroll
                for (int kh = 0; kh < 3; ++kh) {
                    ull W0 = f32x2_bcast(wp[kh * 3 + 0]);
                    ull W1 = f32x2_bcast(wp[kh * 3 + 1]);
                    ull W2 = f32x2_bcast(wp[kh * 3 + 2]);
                    f32x2_fma(acc0[ocl], p[kh][0], W0);
                    f32x2_fma(acc0[ocl], p[kh][1], W1);
                    f32x2_fma(acc0[ocl], p[kh][2], W2);
                    f32x2_fma(acc1[ocl], p[kh][2], W0);
                    f32x2_fma(acc1[ocl], p[kh][3], W1);
                    f32x2_fma(acc1[ocl], p[kh][4], W2);
                }
            }
        }
    }

    // bias + relu + pool (sum over the image's 1024 pixels)
    const int lane = tid & 31, wrp = tid >> 5;
    #pragma unroll
    for (int ocl = 0; ocl < 16; ++ocl) {
        float bb = b2[og * 16 + ocl];
        float v0, v1, v2, v3;
        f32x2_unpack(acc0[ocl], v0, v1);
        f32x2_unpack(acc1[ocl], v2, v3);
        float s = fmaxf(v0 + bb, 0.f) + fmaxf(v1 + bb, 0.f)
                + fmaxf(v2 + bb, 0.f) + fmaxf(v3 + bb, 0.f);
        #pragma unroll
        for (int off = 16; off > 0; off >>= 1) s += __shfl_down_sync(0xffffffffu, s, off);
        if (lane == 0) red[ocl][wrp] = s;
    }
    __syncthreads();
    if (tid < 16) {
        float s = 0.f;
        #pragma unroll
        for (int w = 0; w < 8; ++w) s += red[tid][w];
        g_pool[img * C2O + og * 16 + tid] = s * (1.f / 1024.f);
    }
}

// =============================== fc + mask ====================================
__global__ void fc_kernel(const float* __restrict__ fw,
                          const float* __restrict__ fb,
                          const float* __restrict__ mask) {
    __shared__ float sz[C2O];
    const int r = blockIdx.x;
    const int o = threadIdx.x;     // 256 threads
    if (o < C2O) sz[o] = g_pool[r * C2O + o];
    __syncthreads();
    float accv = fb[o];
    const float* wp = fw + o * C2O;
    #pragma unroll 8
    for (int k = 0; k < C2O; k += 4) {
        float4 wv = *(const float4*)(wp + k);
        accv += sz[k] * wv.x + sz[k + 1] * wv.y + sz[k + 2] * wv.z + sz[k + 3] * wv.w;
    }
    g_h0[r * HID + o] = accv * mask[r];
}

// =============================== row sums =====================================
// STAGE 0: g_h0 -> g_S1   STAGE 1: g_h1 -> g_S2  (globals bound in device code)
template <int STAGE>
__global__ void rowsum_kernel() {
    const float* __restrict__ h = (STAGE == 0) ? g_h0 : g_h1;
    float* __restrict__ S       = (STAGE == 0) ? g_S1 : g_S2;
    const int b = blockIdx.x;
    const int d = threadIdx.x;   // HID threads
    float s = 0.f;
    #pragma unroll 8
    for (int n = 0; n < 32; ++n) s += h[(b * 32 + n) * HID + d];
    S[b * HID + d] = s;
}

// =============================== SAGE layers ==================================
// out[r][o] = sum_d agg[r][d]*lw[o][d] + lb[o] + sum_d h[r][d]*rw[o][d]
// agg[r][d] = (S[b][d] - h[r][d]) / 31
__global__ void sage1_kernel(const float* __restrict__ lw, const float* __restrict__ lb,
                             const float* __restrict__ rw) {
    __shared__ float sh[HID], sa[HID];
    const int r = blockIdx.x;
    const int b = r >> 5;
    {
        const int i = threadIdx.x;   // HID threads: one pass
        float hv = g_h0[r * HID + i];
        sh[i] = hv;
        sa[i] = (g_S1[b * HID + i] - hv) * (1.f / 31.f);
    }
    __syncthreads();
    const int o = threadIdx.x;
    float accv = lb[o];
    const float* lp = lw + o * HID;
    const float* rp = rw + o * HID;
    #pragma unroll 4
    for (int k = 0; k < HID; k += 4) {
        float4 lv = *(const float4*)(lp + k);
        float4 rv = *(const float4*)(rp + k);
        accv += sa[k] * lv.x + sa[k + 1] * lv.y + sa[k + 2] * lv.z + sa[k + 3] * lv.w;
        accv += sh[k] * rv.x + sh[k + 1] * rv.y + sh[k + 2] * rv.z + sh[k + 3] * rv.w;
    }
    g_h1[r * HID + o] = fmaxf(accv, 0.f);
}

__global__ void sage2_kernel(const float* __restrict__ lw, const float* __restrict__ lb,
                             const float* __restrict__ rw, float* __restrict__ out) {
    __shared__ float sh[HID], sa[HID];
    const int r = blockIdx.x;
    const int b = r >> 5;
    for (int i = threadIdx.x; i < HID; i += OUTD) {   // OUTD=128 threads: two passes
        float hv = g_h1[r * HID + i];
        sh[i] = hv;
        sa[i] = (g_S2[b * HID + i] - hv) * (1.f / 31.f);
    }
    __syncthreads();
    const int o = threadIdx.x;
    float accv = lb[o];
    const float* lp = lw + o * HID;
    const float* rp = rw + o * HID;
    #pragma unroll 4
    for (int k = 0; k < HID; k += 4) {
        float4 lv = *(const float4*)(lp + k);
        float4 rv = *(const float4*)(rp + k);
        accv += sa[k] * lv.x + sa[k + 1] * lv.y + sa[k + 2] * lv.z + sa[k + 3] * lv.w;
        accv += sh[k] * rv.x + sh[k + 1] * rv.y + sh[k + 2] * rv.z + sh[k + 3] * rv.w;
    }
    out[r * OUTD + o] = accv;
}

// ================================ launch ======================================
// Pure kernel launches only; graph-capturable. No device-global symbol crosses
// the host/device boundary. Inputs bound BY ELEMENT COUNT (robust to metadata
// order): unique: x=3145728, mask=1024, conv1_w=1728, conv1_b=64, conv2_w=73728
//   by occurrence (same relative order under insertion OR alphabetical order):
//     128: conv2_b, s2_lb   256: fc_b, s1_lb
//     32768: fc_w, s2_lw, s2_rw   65536: s1_lw, s1_rw
extern "C" void kernel_launch(void* const* d_in, const int* in_sizes, int n_in,
                              void* d_out, int out_size) {
    const float *x = 0, *mask = 0, *c1w = 0, *c1b = 0, *c2w = 0;
    const float *c2b = 0, *s2lb = 0;            // 128-group
    const float *fcb = 0, *s1lb = 0;            // 256-group
    const float *fcw = 0, *s2lw = 0, *s2rw = 0; // 32768-group
    const float *s1lw = 0, *s1rw = 0;           // 65536-group
    int n128 = 0, n256 = 0, n32k = 0, n64k = 0;

    for (int i = 0; i < n_in; ++i) {
        const float* p = (const float*)d_in[i];
        switch (in_sizes[i]) {
            case 3145728: x = p; break;
            case 1024:    mask = p; break;
            case 1728:    c1w = p; break;
            case 64:      c1b = p; break;
            case 73728:   c2w = p; break;
            case 128:     if (n128++ == 0) c2b = p; else s2lb = p; break;
            case 256:     if (n256++ == 0) fcb = p; else s1lb = p; break;
            case 32768:
                if (n32k == 0) fcw = p; else if (n32k == 1) s2lw = p; else s2rw = p;
                ++n32k; break;
            case 65536:
                if (n64k++ == 0) s1lw = p; else s1rw = p; break;
            default: break;
        }
    }

    float* out = (float*)d_out;

    conv1_kernel<<<IMGS, 256>>>(x, c1w, c1b);

    dim3 g2(8, IMGS);
    conv2_pool_kernel<<<g2, 256>>>(c2w, c2b);

    fc_kernel<<<IMGS, 256>>>(fcw, fcb, mask);

    rowsum_kernel<0><<<32, HID>>>();
    sage1_kernel<<<IMGS, HID>>>(s1lw, s1lb, s1rw);
    rowsum_kernel<1><<<32, HID>>>();
    sage2_kernel<<<IMGS, OUTD>>>(s2lw, s2lb, s2rw, out);
    (void)out_size;
}